// round 15
// baseline (speedup 1.0000x reference)
#include <cuda_runtime.h>
#include <cuda_bf16.h>

// I2GNN fixed structure: G=64, N_PER_G=64, S=8, DEG=4, EMB=128, LAYERS=5.
// R11: warp tile 32x32 (halves LDSM A traffic), 64-bit message smem ops,
//      residual in registers, bf16x2 messages, bf16 m16n8k16 MMA fp32-acc.

#define NN   4096
#define NPG  64
#define EMB  128
#define S    8
#define NLAY 5
#define NT   64
#define XW   68          // XvB/Agg row stride in u32 words (136 u16)

__device__ float g_lin[NN * EMB];
__device__ float g_node_s[NN];
// bf16 B frags: [layer][ks(8)][wn(4)][lane(32)][8]  (q = nt*2+reg)
__device__ unsigned int g_wfrag[NLAY * 8 * 4 * 32 * 8];

typedef unsigned long long u64;
typedef unsigned int u32;
typedef unsigned short u16;

#define PACKBF(u, lo, hi) \
    asm("cvt.rn.bf16x2.f32 %0, %1, %2;" : "=r"(u) : "f"(hi), "f"(lo))
#define BFFMA2(d, a, b, c) \
    asm("fma.rn.bf16x2 %0, %1, %2, %3;" : "=r"(d) : "r"(a), "r"(b), "r"(c))
#define SPLIT64(lo, hi, q) \
    asm("mov.b64 {%0, %1}, %2;" : "=r"(lo), "=r"(hi) : "l"(q))

#define MMA_BF16(c, a, b0, b1) \
    asm("mma.sync.aligned.m16n8k16.row.col.f32.bf16.bf16.f32 " \
        "{%0,%1,%2,%3}, {%4,%5,%6,%7}, {%8,%9}, {%0,%1,%2,%3};" \
        : "+f"((c)[0]), "+f"((c)[1]), "+f"((c)[2]), "+f"((c)[3]) \
        : "r"((a)[0]), "r"((a)[1]), "r"((a)[2]), "r"((a)[3]), \
          "r"(b0), "r"(b1))

#define LDSM4(r, addr) \
    asm("ldmatrix.sync.aligned.m8n8.x4.shared.b16 {%0,%1,%2,%3}, [%4];" \
        : "=r"((r)[0]), "=r"((r)[1]), "=r"((r)[2]), "=r"((r)[3]) : "r"(addr))

// ---------------------------------------------------------------------------
// element (layer, ks, wn, lane, q): nt=q>>1, reg=q&1
//   col = wn*32 + nt*8 + (lane>>2)
//   k0  = ks*16 + reg*8 + (lane&3)*2 -> pack {W[k0][col], W[k0+1][col]}
__global__ void wfrag_kernel(const float* __restrict__ w_conv) {
    const int idx = blockIdx.x * 256 + threadIdx.x;     // 40960 total
    const int q     = idx & 7;
    const int lane  = (idx >> 3) & 31;
    const int wn    = (idx >> 8) & 3;
    const int ks    = (idx >> 10) & 7;
    const int layer = idx >> 13;
    const int nt = q >> 1, reg = q & 1;
    const int col = wn * 32 + nt * 8 + (lane >> 2);
    const int k0  = ks * 16 + reg * 8 + (lane & 3) * 2;
    const float lo = w_conv[layer * EMB * EMB + k0 * EMB + col];
    const float hi = w_conv[layer * EMB * EMB + (k0 + 1) * EMB + col];
    u32 u; PACKBF(u, lo, hi);
    g_wfrag[idx] = u;
}

// ---------------------------------------------------------------------------
__global__ void lin_kernel(const int* __restrict__ x,
                           const float* __restrict__ emb_x,
                           const float* __restrict__ w_ti,
                           const float* __restrict__ b_ti) {
    __shared__ float sXe[2][EMB];
    const int h = threadIdx.x >> 7;          // node half
    const int i = blockIdx.x * 2 + h;
    const int c = threadIdx.x & 127;
    sXe[h][c] = emb_x[x[i] * EMB + c];
    __syncthreads();
    float a0 = 0.f, a1 = 0.f, a2 = 0.f, a3 = 0.f;
#pragma unroll 8
    for (int k = 0; k < EMB; k += 4) {
        a0 = fmaf(sXe[h][k + 0], w_ti[(k + 0) * EMB + c], a0);
        a1 = fmaf(sXe[h][k + 1], w_ti[(k + 1) * EMB + c], a1);
        a2 = fmaf(sXe[h][k + 2], w_ti[(k + 2) * EMB + c], a2);
        a3 = fmaf(sXe[h][k + 3], w_ti[(k + 3) * EMB + c], a3);
    }
    g_lin[i * EMB + c] = b_ti[c] + ((a0 + a1) + (a2 + a3));
}

// ---------------------------------------------------------------------------
// smem layout (bytes)
#define SMB_XVB 0          // u32[64*68]  17408
#define SMB_AGG 17408      // u32[64*68]  17408
#define SMB_EA  34816      // u32[32*64]   8192
#define SMB_LIN 43008      // f32[8*128]   4096
#define SMB_XE  47104      // f32[128]      512
#define SMB_TF  47616      // int[128]      512
#define SMB_RED 48128      // f32[8]         32
#define SMEM_BYTES 48160

__global__ __launch_bounds__(256, 3)
void conv_kernel(const int* __restrict__ x,
                 const int* __restrict__ edge_attr,
                 const int* __restrict__ tuplefeat,
                 const float* __restrict__ emb_x,
                 const float* __restrict__ emb_ea,
                 const float* __restrict__ emb_tf,
                 const float* __restrict__ b_conv,
                 const float* __restrict__ w_pred) {
    extern __shared__ char smraw[];
    u32*   sXvB = (u32*)(smraw + SMB_XVB);
    u32*   sAgg = (u32*)(smraw + SMB_AGG);
    u32*   sEaB = (u32*)(smraw + SMB_EA);
    float* sLin = (float*)(smraw + SMB_LIN);
    float* sXe  = (float*)(smraw + SMB_XE);
    int*   sTf  = (int*)(smraw + SMB_TF);
    float* sRed = (float*)(smraw + SMB_RED);

    const int i    = blockIdx.x;
    const int tid  = threadIdx.x;
    const int base = (i >> 6) << 6;
    const int im   = i & 63;

    const int wid  = tid >> 5;
    const int lane = tid & 31;
    const int l4   = lane >> 2;
    const int lq   = lane & 3;
    const int wm   = wid & 1;       // m-tile of warp (rows wm*32..+31)
    const int wn   = wid >> 1;      // n-tile of warp (cols wn*32..+31)

    // ldmatrix per-lane address (A frags from sAgg), warp rows wm*32+..
    const int rowsel = (lane & 7) + ((lane >> 3) & 1) * 8;
    const int colsel = (lane >> 4) * 8;
    const u32 aBase = (u32)__cvta_generic_to_shared(sAgg);
    const u32 aAddr = aBase + ((wm * 32 + rowsel) * (XW * 2) + colsel) * 2;

    // ---- stage embeddings ----
    if (tid < EMB) sXe[tid] = emb_x[x[i] * EMB + tid];
    if (tid < 128) sTf[tid] = tuplefeat[i * NT * 2 + tid];

    for (int idx = tid; idx < S * EMB; idx += 256) {
        const int j = idx >> 7, c = idx & 127;
        const int jn = ((im + j) & 63) + base;
        sLin[idx] = g_lin[jn * EMB + c];
    }
    // Ea -> bf16x2 smem: [e(32)][cw(64)]
    for (int idx = tid; idx < 32 * 64; idx += 256) {
        const int e = idx >> 6, cw = idx & 63;
        const int ok = e >> 2, di = e & 3;
        const int kg = ((im + ok) & 63) + base;
        const float* row = emb_ea + edge_attr[kg * 4 + di] * EMB + cw * 2;
        u32 u; PACKBF(u, row[0], row[1]);
        sEaB[idx] = u;
    }
    __syncthreads();

    // ---- XvB init (bf16 smem copy) ----
    for (int idx = tid; idx < NT * 64; idx += 256) {
        const int t = idx >> 6, cw = idx & 63;
        const int c0 = cw * 2;
        const int j = t >> 3;
        const int tfi = sTf[t * 2 + (cw >> 5)];
        const float2 tf2 = *(const float2*)(emb_tf + tfi * 64 + (c0 & 63));
        const float v0 = sXe[c0] * sLin[(j << 7) + c0] * tf2.x;
        const float v1 = sXe[c0 + 1] * sLin[(j << 7) + c0 + 1] * tf2.y;
        u32 u; PACKBF(u, v0, v1);
        sXvB[t * XW + cw] = u;
    }

    // ---- xv register fragment init (exact fp32), 32x32 warp tile ----
    float xv[2][4][4];
#pragma unroll
    for (int mt = 0; mt < 2; ++mt)
#pragma unroll
        for (int nt = 0; nt < 4; ++nt)
#pragma unroll
            for (int r = 0; r < 4; ++r) {
                const int row = wm * 32 + mt * 16 + ((r >> 1) & 1) * 8 + l4;
                const int col = wn * 32 + nt * 8 + 2 * lq + (r & 1);
                const int tfi = sTf[row * 2 + (col >> 6)];
                const float tfv = emb_tf[tfi * 64 + (col & 63)];
                xv[mt][nt][r] = sXe[col] * sLin[((row >> 3) << 7) + col] * tfv;
            }
    __syncthreads();

    const int mk = wid;                 // message k owned by this warp
    const u32* wfbase = g_wfrag + wn * 256 + lane * 8;

    for (int layer = 0; layer < NLAY; ++layer) {
        const float* __restrict__ B = b_conv + layer * EMB;
        const u32* wf = wfbase + layer * 8192;   // + ks*1024

        // --- messages, bf16x2, 64-bit smem accesses ---
        {
            const u32* ea = sEaB + (mk << 8) + lane * 2;
            u32 e0a, e0b, e1a, e1b, e2a, e2b, e3a, e3b;
            SPLIT64(e0a, e0b, *(const u64*)(ea));
            SPLIT64(e1a, e1b, *(const u64*)(ea + 64));
            SPLIT64(e2a, e2b, *(const u64*)(ea + 128));
            SPLIT64(e3a, e3b, *(const u64*)(ea + 192));
#pragma unroll
            for (int j = 0; j < S; ++j) {
                const int t = (j << 3) + mk;
                u32 a = 0u, b = 0u;
                u32 xl, xh;
                if (mk < 7) {
                    SPLIT64(xl, xh, *(const u64*)&sXvB[(t + 1) * XW + lane * 2]);
                    BFFMA2(a, xl, e0a, a); BFFMA2(b, xh, e0b, b);
                }
                if (mk < 6) {
                    SPLIT64(xl, xh, *(const u64*)&sXvB[(t + 2) * XW + lane * 2]);
                    BFFMA2(a, xl, e1a, a); BFFMA2(b, xh, e1b, b);
                }
                if (mk > 0) {
                    SPLIT64(xl, xh, *(const u64*)&sXvB[(t - 1) * XW + lane * 2]);
                    BFFMA2(a, xl, e2a, a); BFFMA2(b, xh, e2b, b);
                }
                if (mk > 1) {
                    SPLIT64(xl, xh, *(const u64*)&sXvB[(t - 2) * XW + lane * 2]);
                    BFFMA2(a, xl, e3a, a); BFFMA2(b, xh, e3b, b);
                }
                *(u64*)&sAgg[t * XW + lane * 2] = ((u64)b << 32) | a;
            }
        }
        __syncthreads();

        // --- GEMM: warp = 32 rows x 32 cols ---
        float acc[2][4][4];
#pragma unroll
        for (int mt = 0; mt < 2; ++mt)
#pragma unroll
            for (int nt = 0; nt < 4; ++nt)
#pragma unroll
                for (int r = 0; r < 4; ++r) acc[mt][nt][r] = 0.f;

        uint4 ba = *(const uint4*)(wf);
        uint4 bb = *(const uint4*)(wf + 4);
#pragma unroll
        for (int ks = 0; ks < 8; ++ks) {
            uint4 nba, nbb;
            if (ks < 7) {
                nba = *(const uint4*)(wf + (ks + 1) * 1024);
                nbb = *(const uint4*)(wf + (ks + 1) * 1024 + 4);
            }
#pragma unroll
            for (int mt = 0; mt < 2; ++mt) {
                u32 afr[4];
                LDSM4(afr, aAddr + (mt * 16 * (XW * 2) + ks * 16) * 2);
                MMA_BF16(acc[mt][0], afr, ba.x, ba.y);
                MMA_BF16(acc[mt][1], afr, ba.z, ba.w);
                MMA_BF16(acc[mt][2], afr, bb.x, bb.y);
                MMA_BF16(acc[mt][3], afr, bb.z, bb.w);
            }
            ba = nba; bb = nbb;
        }

        // --- epilogue: xv += relu(acc + b); pack bf16 -> sXvB ---
        const int col0 = wn * 32 + 2 * lq;
#pragma unroll
        for (int nt = 0; nt < 4; ++nt) {
            const float2 bbv = *(const float2*)(B + col0 + nt * 8);
#pragma unroll
            for (int mt = 0; mt < 2; ++mt) {
                const int row = wm * 32 + mt * 16 + l4;
                float v0 = acc[mt][nt][0] + bbv.x; v0 = v0 > 0.f ? v0 : 0.f;
                float v1 = acc[mt][nt][1] + bbv.y; v1 = v1 > 0.f ? v1 : 0.f;
                float v2 = acc[mt][nt][2] + bbv.x; v2 = v2 > 0.f ? v2 : 0.f;
                float v3 = acc[mt][nt][3] + bbv.y; v3 = v3 > 0.f ? v3 : 0.f;
                xv[mt][nt][0] += v0;
                xv[mt][nt][1] += v1;
                xv[mt][nt][2] += v2;
                xv[mt][nt][3] += v3;
                u32 u0, u1;
                PACKBF(u0, xv[mt][nt][0], xv[mt][nt][1]);
                PACKBF(u1, xv[mt][nt][2], xv[mt][nt][3]);
                const int w0 = row * XW + wn * 16 + nt * 4 + lq;
                sXvB[w0] = u0;
                sXvB[w0 + 8 * XW] = u1;
            }
        }
        __syncthreads();
    }

    // --- pooling in registers: max over k (l4 lanes) then sum over j ---
    float node8[4][2] = {{0.f,0.f},{0.f,0.f},{0.f,0.f},{0.f,0.f}};
#pragma unroll
    for (int mt = 0; mt < 2; ++mt)
#pragma unroll
        for (int nt = 0; nt < 4; ++nt)
#pragma unroll
            for (int r = 0; r < 4; ++r) {
                float v = xv[mt][nt][r];
                v = fmaxf(v, __shfl_xor_sync(0xffffffffu, v, 4));
                v = fmaxf(v, __shfl_xor_sync(0xffffffffu, v, 8));
                v = fmaxf(v, __shfl_xor_sync(0xffffffffu, v, 16));
                node8[nt][r & 1] += v;     // sums over mt and row-half (= j)
            }
    const int colb = wn * 32 + 2 * lq;
    float part = 0.f;
#pragma unroll
    for (int nt = 0; nt < 4; ++nt)
        part += node8[nt][0] * w_pred[colb + nt * 8]
              + node8[nt][1] * w_pred[colb + nt * 8 + 1];
    if (l4 != 0) part = 0.f;
#pragma unroll
    for (int o = 16; o; o >>= 1) part += __shfl_down_sync(0xffffffffu, part, o);
    if (lane == 0) sRed[wid] = part;
    __syncthreads();
    if (tid == 0) {
        float s = 0.f;
#pragma unroll
        for (int w = 0; w < 8; ++w) s += sRed[w];
        g_node_s[i] = s;
    }
}

// ---------------------------------------------------------------------------
__global__ void final_kernel(const float* __restrict__ b_pred,
                             float* __restrict__ out) {
    __shared__ float sp[2];
    const int g = blockIdx.x;
    const int t = threadIdx.x;       // 64
    float v = g_node_s[g * NPG + t];
#pragma unroll
    for (int o = 16; o; o >>= 1) v += __shfl_down_sync(0xffffffffu, v, o);
    if ((t & 31) == 0) sp[t >> 5] = v;
    __syncthreads();
    if (t == 0) out[g] = sp[0] + sp[1] + b_pred[0];
}

// ---------------------------------------------------------------------------
extern "C" void kernel_launch(void* const* d_in, const int* in_sizes, int n_in,
                              void* d_out, int out_size) {
    const int* x         = (const int*)d_in[0];
    const int* edge_attr = (const int*)d_in[1];
    const int* tuplefeat = (const int*)d_in[2];
    int w0 = (n_in >= 21 && in_sizes[11] == 1) ? 12 : 11;
    const float* emb_x  = (const float*)d_in[w0 + 0];
    const float* emb_ea = (const float*)d_in[w0 + 1];
    const float* emb_tf = (const float*)d_in[w0 + 2];
    const float* w_ti   = (const float*)d_in[w0 + 3];
    const float* b_ti   = (const float*)d_in[w0 + 4];
    const float* w_conv = (const float*)d_in[w0 + 5];
    const float* b_conv = (const float*)d_in[w0 + 6];
    const float* w_pred = (const float*)d_in[w0 + 7];
    const float* b_pred = (const float*)d_in[w0 + 8];
    float* out = (float*)d_out;

    cudaFuncSetAttribute(conv_kernel,
                         cudaFuncAttributeMaxDynamicSharedMemorySize, SMEM_BYTES);

    wfrag_kernel<<<NLAY * 8 * 4 * 32 * 8 / 256, 256>>>(w_conv);
    lin_kernel<<<NN / 2, 256>>>(x, emb_x, w_ti, b_ti);
    conv_kernel<<<NN, 256, SMEM_BYTES>>>(x, edge_attr, tuplefeat,
                                         emb_x, emb_ea, emb_tf,
                                         b_conv, w_pred);
    final_kernel<<<NPG, NPG>>>(b_pred, out);
}

// round 17
// speedup vs baseline: 1.1058x; 1.1058x over previous
#include <cuda_runtime.h>
#include <cuda_bf16.h>

// I2GNN fixed structure: G=64, N_PER_G=64, S=8, DEG=4, EMB=128, LAYERS=5.
// R12 = R10 (warp tile 64x16, rolling B prefetch, registers-resident residual,
//       bf16x2 messages, register pooling) + 64-bit message smem accesses
//       (bank-conflict fix) + 2-node lin blocks.

#define NN   4096
#define NPG  64
#define EMB  128
#define S    8
#define NLAY 5
#define NT   64
#define XW   68          // XvB/Agg row stride in u32 words (136 u16)

__device__ float g_lin[NN * EMB];
__device__ float g_node_s[NN];
// bf16 B frags: [layer][warp(8)][ks(8)][lane(32)][4]
__device__ unsigned int g_wfrag[NLAY * 8 * 8 * 32 * 4];

typedef unsigned long long u64;
typedef unsigned int u32;
typedef unsigned short u16;

#define PACKBF(u, lo, hi) \
    asm("cvt.rn.bf16x2.f32 %0, %1, %2;" : "=r"(u) : "f"(hi), "f"(lo))
#define BFFMA2(d, a, b, c) \
    asm("fma.rn.bf16x2 %0, %1, %2, %3;" : "=r"(d) : "r"(a), "r"(b), "r"(c))
#define SPLIT64(lo, hi, q) \
    asm("mov.b64 {%0, %1}, %2;" : "=r"(lo), "=r"(hi) : "l"(q))

#define MMA_BF16(c, a, b0, b1) \
    asm("mma.sync.aligned.m16n8k16.row.col.f32.bf16.bf16.f32 " \
        "{%0,%1,%2,%3}, {%4,%5,%6,%7}, {%8,%9}, {%0,%1,%2,%3};" \
        : "+f"((c)[0]), "+f"((c)[1]), "+f"((c)[2]), "+f"((c)[3]) \
        : "r"((a)[0]), "r"((a)[1]), "r"((a)[2]), "r"((a)[3]), \
          "r"(b0), "r"(b1))

#define LDSM4(r, addr) \
    asm("ldmatrix.sync.aligned.m8n8.x4.shared.b16 {%0,%1,%2,%3}, [%4];" \
        : "=r"((r)[0]), "=r"((r)[1]), "=r"((r)[2]), "=r"((r)[3]) : "r"(addr))

// ---------------------------------------------------------------------------
// element (layer, w, ks, lane, r): nt=r>>1, reg=r&1
//   col = w*16 + nt*8 + (lane>>2)
//   k0  = ks*16 + reg*8 + (lane&3)*2 -> pack {W[k0][col], W[k0+1][col]}
__global__ void wfrag_kernel(const float* __restrict__ w_conv) {
    const int idx = blockIdx.x * 256 + threadIdx.x;     // 40960 total
    const int r     = idx & 3;
    const int lane  = (idx >> 2) & 31;
    const int ks    = (idx >> 7) & 7;
    const int w     = (idx >> 10) & 7;
    const int layer = idx >> 13;
    const int nt = r >> 1, reg = r & 1;
    const int col = w * 16 + nt * 8 + (lane >> 2);
    const int k0  = ks * 16 + reg * 8 + (lane & 3) * 2;
    const float lo = w_conv[layer * EMB * EMB + k0 * EMB + col];
    const float hi = w_conv[layer * EMB * EMB + (k0 + 1) * EMB + col];
    u32 u; PACKBF(u, lo, hi);
    g_wfrag[idx] = u;
}

// ---------------------------------------------------------------------------
__global__ void lin_kernel(const int* __restrict__ x,
                           const float* __restrict__ emb_x,
                           const float* __restrict__ w_ti,
                           const float* __restrict__ b_ti) {
    __shared__ float sXe[2][EMB];
    const int h = threadIdx.x >> 7;          // node half
    const int i = blockIdx.x * 2 + h;
    const int c = threadIdx.x & 127;
    sXe[h][c] = emb_x[x[i] * EMB + c];
    __syncthreads();
    float a0 = 0.f, a1 = 0.f, a2 = 0.f, a3 = 0.f;
#pragma unroll 8
    for (int k = 0; k < EMB; k += 4) {
        a0 = fmaf(sXe[h][k + 0], w_ti[(k + 0) * EMB + c], a0);
        a1 = fmaf(sXe[h][k + 1], w_ti[(k + 1) * EMB + c], a1);
        a2 = fmaf(sXe[h][k + 2], w_ti[(k + 2) * EMB + c], a2);
        a3 = fmaf(sXe[h][k + 3], w_ti[(k + 3) * EMB + c], a3);
    }
    g_lin[i * EMB + c] = b_ti[c] + ((a0 + a1) + (a2 + a3));
}

// ---------------------------------------------------------------------------
// smem layout (bytes)
#define SMB_XVB 0          // u32[64*68]  17408
#define SMB_AGG 17408      // u32[64*68]  17408
#define SMB_EA  34816      // u32[32*64]   8192
#define SMB_LIN 43008      // f32[8*128]   4096
#define SMB_XE  47104      // f32[128]      512
#define SMB_TF  47616      // int[128]      512
#define SMB_RED 48128      // f32[8]         32
#define SMEM_BYTES 48160

__global__ __launch_bounds__(256, 3)
void conv_kernel(const int* __restrict__ x,
                 const int* __restrict__ edge_attr,
                 const int* __restrict__ tuplefeat,
                 const float* __restrict__ emb_x,
                 const float* __restrict__ emb_ea,
                 const float* __restrict__ emb_tf,
                 const float* __restrict__ b_conv,
                 const float* __restrict__ w_pred) {
    extern __shared__ char smraw[];
    u32*   sXvB = (u32*)(smraw + SMB_XVB);
    u32*   sAgg = (u32*)(smraw + SMB_AGG);
    u32*   sEaB = (u32*)(smraw + SMB_EA);
    float* sLin = (float*)(smraw + SMB_LIN);
    float* sXe  = (float*)(smraw + SMB_XE);
    int*   sTf  = (int*)(smraw + SMB_TF);
    float* sRed = (float*)(smraw + SMB_RED);

    const int i    = blockIdx.x;
    const int tid  = threadIdx.x;
    const int base = (i >> 6) << 6;
    const int im   = i & 63;

    const int wid  = tid >> 5;
    const int lane = tid & 31;
    const int l4   = lane >> 2;
    const int lq   = lane & 3;

    // ldmatrix per-lane address (A frags from sAgg)
    const int rowsel = (lane & 7) + ((lane >> 3) & 1) * 8;
    const int colsel = (lane >> 4) * 8;
    const u32 aBase = (u32)__cvta_generic_to_shared(sAgg);
    const u32 aAddr = aBase + (rowsel * (XW * 2) + colsel) * 2;

    // ---- stage embeddings ----
    if (tid < EMB) sXe[tid] = emb_x[x[i] * EMB + tid];
    if (tid < 128) sTf[tid] = tuplefeat[i * NT * 2 + tid];

    for (int idx = tid; idx < S * EMB; idx += 256) {
        const int j = idx >> 7, c = idx & 127;
        const int jn = ((im + j) & 63) + base;
        sLin[idx] = g_lin[jn * EMB + c];
    }
    // Ea -> bf16x2 smem: [e(32)][cw(64)]
    for (int idx = tid; idx < 32 * 64; idx += 256) {
        const int e = idx >> 6, cw = idx & 63;
        const int ok = e >> 2, di = e & 3;
        const int kg = ((im + ok) & 63) + base;
        const float* row = emb_ea + edge_attr[kg * 4 + di] * EMB + cw * 2;
        u32 u; PACKBF(u, row[0], row[1]);
        sEaB[idx] = u;
    }
    __syncthreads();

    // ---- XvB init (bf16 smem copy) ----
    for (int idx = tid; idx < NT * 64; idx += 256) {
        const int t = idx >> 6, cw = idx & 63;
        const int c0 = cw * 2;
        const int j = t >> 3;
        const int tfi = sTf[t * 2 + (cw >> 5)];
        const float2 tf2 = *(const float2*)(emb_tf + tfi * 64 + (c0 & 63));
        const float v0 = sXe[c0] * sLin[(j << 7) + c0] * tf2.x;
        const float v1 = sXe[c0 + 1] * sLin[(j << 7) + c0 + 1] * tf2.y;
        u32 u; PACKBF(u, v0, v1);
        sXvB[t * XW + cw] = u;
    }

    // ---- xv register fragment init (exact fp32) ----
    float xv[4][2][4];
#pragma unroll
    for (int mt = 0; mt < 4; ++mt)
#pragma unroll
        for (int nt = 0; nt < 2; ++nt)
#pragma unroll
            for (int r = 0; r < 4; ++r) {
                const int row = mt * 16 + ((r >> 1) & 1) * 8 + l4;
                const int col = wid * 16 + nt * 8 + 2 * lq + (r & 1);
                const int tfi = sTf[row * 2 + (col >> 6)];
                const float tfv = emb_tf[tfi * 64 + (col & 63)];
                xv[mt][nt][r] = sXe[col] * sLin[((row >> 3) << 7) + col] * tfv;
            }
    __syncthreads();

    const int mk = wid;                 // message k owned by this warp
    const u32* wfbase = g_wfrag + wid * 1024 + lane * 4;

    for (int layer = 0; layer < NLAY; ++layer) {
        const float* __restrict__ B = b_conv + layer * EMB;
        const u32* wf = wfbase + layer * 8192;

        // --- messages, bf16x2, 64-bit smem accesses (conflict-free) ---
        {
            const u32* ea = sEaB + (mk << 8) + lane * 2;
            u32 e0a, e0b, e1a, e1b, e2a, e2b, e3a, e3b;
            SPLIT64(e0a, e0b, *(const u64*)(ea));
            SPLIT64(e1a, e1b, *(const u64*)(ea + 64));
            SPLIT64(e2a, e2b, *(const u64*)(ea + 128));
            SPLIT64(e3a, e3b, *(const u64*)(ea + 192));
#pragma unroll
            for (int j = 0; j < S; ++j) {
                const int t = (j << 3) + mk;
                u32 a = 0u, b = 0u;
                u32 xl, xh;
                if (mk < 7) {
                    SPLIT64(xl, xh, *(const u64*)&sXvB[(t + 1) * XW + lane * 2]);
                    BFFMA2(a, xl, e0a, a); BFFMA2(b, xh, e0b, b);
                }
                if (mk < 6) {
                    SPLIT64(xl, xh, *(const u64*)&sXvB[(t + 2) * XW + lane * 2]);
                    BFFMA2(a, xl, e1a, a); BFFMA2(b, xh, e1b, b);
                }
                if (mk > 0) {
                    SPLIT64(xl, xh, *(const u64*)&sXvB[(t - 1) * XW + lane * 2]);
                    BFFMA2(a, xl, e2a, a); BFFMA2(b, xh, e2b, b);
                }
                if (mk > 1) {
                    SPLIT64(xl, xh, *(const u64*)&sXvB[(t - 2) * XW + lane * 2]);
                    BFFMA2(a, xl, e3a, a); BFFMA2(b, xh, e3b, b);
                }
                *(u64*)&sAgg[t * XW + lane * 2] = ((u64)b << 32) | a;
            }
        }
        __syncthreads();

        // --- GEMM: warp = 64 rows x 16 cols, rolling B prefetch ---
        float acc[4][2][4];
#pragma unroll
        for (int mt = 0; mt < 4; ++mt)
#pragma unroll
            for (int nt = 0; nt < 2; ++nt)
#pragma unroll
                for (int r = 0; r < 4; ++r) acc[mt][nt][r] = 0.f;

        uint4 bq[3];
        bq[0] = *(const uint4*)(wf);
        bq[1] = *(const uint4*)(wf + 128);
#pragma unroll
        for (int ks = 0; ks < 8; ++ks) {
            if (ks < 6) bq[(ks + 2) % 3] = *(const uint4*)(wf + (ks + 2) * 128);
            const uint4 bb = bq[ks % 3];
#pragma unroll
            for (int mt = 0; mt < 4; ++mt) {
                u32 afr[4];
                LDSM4(afr, aAddr + (mt * 16 * XW * 2 + ks * 16) * 2);
                MMA_BF16(acc[mt][0], afr, bb.x, bb.y);
                MMA_BF16(acc[mt][1], afr, bb.z, bb.w);
            }
        }

        // --- epilogue: xv += relu(acc + b); pack bf16 -> sXvB ---
        const int col0 = wid * 16 + 2 * lq;
        const float2 bb0 = *(const float2*)(B + col0);
        const float2 bb1 = *(const float2*)(B + col0 + 8);
#pragma unroll
        for (int mt = 0; mt < 4; ++mt) {
            const int row = mt * 16 + l4;
#pragma unroll
            for (int nt = 0; nt < 2; ++nt) {
                const float bx = nt ? bb1.x : bb0.x;
                const float by = nt ? bb1.y : bb0.y;
                float v0 = acc[mt][nt][0] + bx; v0 = v0 > 0.f ? v0 : 0.f;
                float v1 = acc[mt][nt][1] + by; v1 = v1 > 0.f ? v1 : 0.f;
                float v2 = acc[mt][nt][2] + bx; v2 = v2 > 0.f ? v2 : 0.f;
                float v3 = acc[mt][nt][3] + by; v3 = v3 > 0.f ? v3 : 0.f;
                xv[mt][nt][0] += v0;
                xv[mt][nt][1] += v1;
                xv[mt][nt][2] += v2;
                xv[mt][nt][3] += v3;
                u32 u0, u1;
                PACKBF(u0, xv[mt][nt][0], xv[mt][nt][1]);
                PACKBF(u1, xv[mt][nt][2], xv[mt][nt][3]);
                const int w0 = row * XW + wid * 8 + nt * 4 + lq;
                sXvB[w0] = u0;
                sXvB[w0 + 8 * XW] = u1;
            }
        }
        __syncthreads();
    }

    // --- pooling in registers: max over k (l4 lanes) then sum over j ---
    float node2[2][2] = {{0.f, 0.f}, {0.f, 0.f}};
#pragma unroll
    for (int mt = 0; mt < 4; ++mt)
#pragma unroll
        for (int nt = 0; nt < 2; ++nt)
#pragma unroll
            for (int r = 0; r < 4; ++r) {
                float v = xv[mt][nt][r];
                v = fmaxf(v, __shfl_xor_sync(0xffffffffu, v, 4));
                v = fmaxf(v, __shfl_xor_sync(0xffffffffu, v, 8));
                v = fmaxf(v, __shfl_xor_sync(0xffffffffu, v, 16));
                node2[nt][r & 1] += v;     // sums over mt and row-half (= j)
            }
    const int colb = wid * 16 + 2 * lq;
    float part = node2[0][0] * w_pred[colb]
               + node2[0][1] * w_pred[colb + 1]
               + node2[1][0] * w_pred[colb + 8]
               + node2[1][1] * w_pred[colb + 9];
    if (l4 != 0) part = 0.f;
#pragma unroll
    for (int o = 16; o; o >>= 1) part += __shfl_down_sync(0xffffffffu, part, o);
    if (lane == 0) sRed[wid] = part;
    __syncthreads();
    if (tid == 0) {
        float s = 0.f;
#pragma unroll
        for (int w = 0; w < 8; ++w) s += sRed[w];
        g_node_s[i] = s;
    }
}

// ---------------------------------------------------------------------------
__global__ void final_kernel(const float* __restrict__ b_pred,
                             float* __restrict__ out) {
    __shared__ float sp[2];
    const int g = blockIdx.x;
    const int t = threadIdx.x;       // 64
    float v = g_node_s[g * NPG + t];
#pragma unroll
    for (int o = 16; o; o >>= 1) v += __shfl_down_sync(0xffffffffu, v, o);
    if ((t & 31) == 0) sp[t >> 5] = v;
    __syncthreads();
    if (t == 0) out[g] = sp[0] + sp[1] + b_pred[0];
}

// ---------------------------------------------------------------------------
extern "C" void kernel_launch(void* const* d_in, const int* in_sizes, int n_in,
                              void* d_out, int out_size) {
    const int* x         = (const int*)d_in[0];
    const int* edge_attr = (const int*)d_in[1];
    const int* tuplefeat = (const int*)d_in[2];
    int w0 = (n_in >= 21 && in_sizes[11] == 1) ? 12 : 11;
    const float* emb_x  = (const float*)d_in[w0 + 0];
    const float* emb_ea = (const float*)d_in[w0 + 1];
    const float* emb_tf = (const float*)d_in[w0 + 2];
    const float* w_ti   = (const float*)d_in[w0 + 3];
    const float* b_ti   = (const float*)d_in[w0 + 4];
    const float* w_conv = (const float*)d_in[w0 + 5];
    const float* b_conv = (const float*)d_in[w0 + 6];
    const float* w_pred = (const float*)d_in[w0 + 7];
    const float* b_pred = (const float*)d_in[w0 + 8];
    float* out = (float*)d_out;

    cudaFuncSetAttribute(conv_kernel,
                         cudaFuncAttributeMaxDynamicSharedMemorySize, SMEM_BYTES);

    wfrag_kernel<<<NLAY * 8 * 8 * 32 * 4 / 256, 256>>>(w_conv);
    lin_kernel<<<NN / 2, 256>>>(x, emb_x, w_ti, b_ti);
    conv_kernel<<<NN, 256, SMEM_BYTES>>>(x, edge_attr, tuplefeat,
                                         emb_x, emb_ea, emb_tf,
                                         b_conv, w_pred);
    final_kernel<<<NPG, NPG>>>(b_pred, out);
}